// round 12
// baseline (speedup 1.0000x reference)
#include <cuda_runtime.h>
#include <cuda_bf16.h>
#include <cuda_fp16.h>
#include <math.h>
#include <stdint.h>

// Problem constants
#define NPTS 8192
#define DIM  512
#define KNN  15
#define KEEP 24     // approx candidates kept per row (margin for bf16+fp16 error)
#define NPAIR 105   // 15*14/2
#define FULLM 0xFFFFFFFFu

// ---------------- scratch (device globals: no allocation allowed) -------------
__device__ __align__(16) __half g_sqd[(size_t)NPTS * NPTS];      // 128 MB approx sq dists
__device__ float  g_norms[NPTS];
__device__ __align__(16) __nv_bfloat16 g_H[(size_t)NPTS * DIM];  // bf16 embeddings
__device__ int    g_knni[NPTS * KNN];
__device__ double g_acc[2];                        // [0]=curv sumsq, [1]=ang sumsq

// ================= PTX helpers (generic sm_80+ only; NO tcgen05) =================
__device__ __forceinline__ uint32_t smem_u32(const void* p) {
    uint32_t a;
    asm("{ .reg .u64 t; cvta.to.shared.u64 t, %1; cvt.u32.u64 %0, t; }" : "=r"(a) : "l"(p));
    return a;
}
__device__ __forceinline__ void cp_async16(uint32_t dst, const void* src) {
    asm volatile("cp.async.cg.shared.global [%0], [%1], 16;" :: "r"(dst), "l"(src));
}
#define CP_COMMIT() asm volatile("cp.async.commit_group;" ::: "memory")

__device__ __forceinline__ void ldmat4(uint32_t* r, uint32_t saddr) {
    asm volatile("ldmatrix.sync.aligned.m8n8.x4.shared.b16 {%0,%1,%2,%3}, [%4];"
                 : "=r"(r[0]), "=r"(r[1]), "=r"(r[2]), "=r"(r[3]) : "r"(saddr));
}
__device__ __forceinline__ void mma_bf16(float* d, const uint32_t* a,
                                         uint32_t b0, uint32_t b1) {
    asm volatile(
        "mma.sync.aligned.m16n8k16.row.col.f32.bf16.bf16.f32 "
        "{%0,%1,%2,%3}, {%4,%5,%6,%7}, {%8,%9}, {%0,%1,%2,%3};"
        : "+f"(d[0]), "+f"(d[1]), "+f"(d[2]), "+f"(d[3])
        : "r"(a[0]), "r"(a[1]), "r"(a[2]), "r"(a[3]), "r"(b0), "r"(b1));
}

// ================= kernel 0: zero accumulators =================
__global__ void zero_acc_kernel() {
    g_acc[0] = 0.0; g_acc[1] = 0.0;
}

// ================= kernel 1: norms (fp32) + bf16 convert, one read of E ========
__global__ void prep_kernel(const float* __restrict__ E) {
    int row  = blockIdx.x * 8 + (threadIdx.x >> 5);
    int lane = threadIdx.x & 31;
    const float4* r = (const float4*)(E + (size_t)row * DIM);
    __nv_bfloat162* H2 = (__nv_bfloat162*)(g_H + (size_t)row * DIM);
    float s = 0.f;
    #pragma unroll
    for (int c4 = lane; c4 < DIM / 4; c4 += 32) {
        float4 v = r[c4];
        s = fmaf(v.x, v.x, fmaf(v.y, v.y, fmaf(v.z, v.z, fmaf(v.w, v.w, s))));
        H2[c4 * 2]     = __floats2bfloat162_rn(v.x, v.y);
        H2[c4 * 2 + 1] = __floats2bfloat162_rn(v.z, v.w);
    }
    #pragma unroll
    for (int o = 16; o; o >>= 1) s += __shfl_xor_sync(FULLM, s, o);
    if (!lane) g_norms[row] = s;
}

// ================= kernel 2: bf16 mma.sync Gram -> approx sq dists (fp16) =======
// CTA tile 128x256, BK=32, 8 warps @ 64x64, fp32 accum.
// Triangular grid at 128x256 granularity: keep (r, c) with 2c <= r (1056 tiles).
// Each 128-col half classified: LOWER (store+mirror), DIAG (store, i==j INF),
// UPPER (skip; covered by another tile's mirror).
#define SROW 80                 // 64B data + 16B pad per K-slab row
#define STAGEB (384 * SROW)     // A(128 rows) + B(256 rows) = 30720 B
#define MIRS 136                // S transpose stride (halves)
#define SMEM_GEMM (256 * MIRS * 2 > 2 * STAGEB ? 256 * MIRS * 2 : 2 * STAGEB)  // 69632

__global__ void __launch_bounds__(256, 1) gemm_bf16_kernel() {
    extern __shared__ __align__(128) char sbuf[];
    const uint32_t sb = smem_u32(sbuf);
    const int tid  = threadIdx.x;
    const int lane = tid & 31;
    const int wid  = tid >> 5;

    // triangular decode at (r:128-row, c:256-col) granularity: 2c <= r
    // cum(2m)=m^2+m, cum(2m+1)=(m+1)^2
    int t = blockIdx.x;
    int r = 2 * (int)sqrtf((float)t);
    if (r > 63) r = 63;
    #pragma unroll 1
    while (r < 63) {
        int rn = r + 1, m = rn >> 1;
        int cm = (rn & 1) ? (m + 1) * (m + 1) : m * m + m;
        if (cm <= t) r = rn; else break;
    }
    #pragma unroll 1
    for (;;) {
        int m = r >> 1;
        int cm = (r & 1) ? (m + 1) * (m + 1) : m * m + m;
        if (cm > t) r--; else break;
    }
    int m0 = r >> 1;
    int cumr = (r & 1) ? (m0 + 1) * (m0 + 1) : m0 * m0 + m0;
    int c = t - cumr;

    const int row0 = r * 128, col0 = c * 256;
    const int wm = (wid >> 2) * 64;       // warp m offset: 0 or 64
    const int wn = (wid & 3) * 64;        // warp n offset: 0,64,128,192
    const int hw = wn >> 7;               // warp's half (0 or 1)

    // half classification
    const bool low0 = (col0 + 128) <= row0;     // left half strictly lower
    const bool low1 = (col0 + 256) <= row0;     // right half strictly lower
    const bool upH  = hw ? (col0 + 128 > row0) : false;   // this warp's half upper?
    const bool lowH = hw ? low1 : low0;

    float d[4][8][4];
    #pragma unroll
    for (int mt = 0; mt < 4; mt++)
        #pragma unroll
        for (int nt = 0; nt < 8; nt++)
            #pragma unroll
            for (int q = 0; q < 4; q++) d[mt][nt][q] = 0.f;

    // cp.async mapping: 384 rows x 4 x 16B chunks = 1536 chunks, 6/thread
    // prologue: stage 0
    {
        uint32_t s0 = sb;
        #pragma unroll
        for (int i = 0; i < 6; i++) {
            int q = tid + i * 256;
            int rw = q >> 2, cc = q & 3;
            const __nv_bfloat16* src = (rw < 128)
                ? &g_H[(size_t)(row0 + rw) * DIM + cc * 8]
                : &g_H[(size_t)(col0 + rw - 128) * DIM + cc * 8];
            cp_async16(s0 + rw * SROW + cc * 16, src);
        }
        CP_COMMIT();
    }

    for (int st = 0; st < 16; st++) {
        if (st < 15) {
            int kk = (st + 1) * 32;
            uint32_t s1 = sb + ((st + 1) & 1) * STAGEB;
            #pragma unroll
            for (int i = 0; i < 6; i++) {
                int q = tid + i * 256;
                int rw = q >> 2, cc = q & 3;
                const __nv_bfloat16* src = (rw < 128)
                    ? &g_H[(size_t)(row0 + rw) * DIM + kk + cc * 8]
                    : &g_H[(size_t)(col0 + rw - 128) * DIM + kk + cc * 8];
                cp_async16(s1 + rw * SROW + cc * 16, src);
            }
            CP_COMMIT();
            asm volatile("cp.async.wait_group 1;" ::: "memory");
        } else {
            asm volatile("cp.async.wait_group 0;" ::: "memory");
        }
        __syncthreads();

        uint32_t aT = sb + (st & 1) * STAGEB;
        uint32_t bT = aT + 128 * SROW;
        #pragma unroll
        for (int ks = 0; ks < 2; ks++) {
            int kb = ks * 32;
            uint32_t aF[4][4], bF[4][4];
            #pragma unroll
            for (int mt = 0; mt < 4; mt++)
                ldmat4(aF[mt], aT + (wm + mt * 16 + (lane & 15)) * SROW + kb + (lane >> 4) * 16);
            #pragma unroll
            for (int g = 0; g < 4; g++)
                ldmat4(bF[g], bT + (wn + g * 16 + (lane & 15)) * SROW + kb + (lane >> 4) * 16);
            #pragma unroll
            for (int mt = 0; mt < 4; mt++)
                #pragma unroll
                for (int nt = 0; nt < 8; nt++)
                    mma_bf16(d[mt][nt], aF[mt], bF[nt >> 1][nt & 1], bF[nt >> 1][(nt & 1) + 2]);
        }
        __syncthreads();
    }

    // ---------------- epilogue ----------------
    const float INF = __int_as_float(0x7f800000);
    __half* S = (__half*)sbuf;     // [256][MIRS] transpose staging (reuses pipeline smem)

    #pragma unroll
    for (int mt = 0; mt < 4; mt++) {
        int i0 = row0 + wm + mt * 16 + (lane >> 2);
        int i1 = i0 + 8;
        float n0 = g_norms[i0], n1 = g_norms[i1];
        #pragma unroll
        for (int nt = 0; nt < 8; nt++) {
            int jl = wn + nt * 8 + (lane & 3) * 2;   // local col in 256-wide tile
            int j0 = col0 + jl;
            float ja = g_norms[j0], jb = g_norms[j0 + 1];
            float o00 = fmaxf(n0 + ja - 2.f * d[mt][nt][0], 0.f);
            float o01 = fmaxf(n0 + jb - 2.f * d[mt][nt][1], 0.f);
            float o10 = fmaxf(n1 + ja - 2.f * d[mt][nt][2], 0.f);
            float o11 = fmaxf(n1 + jb - 2.f * d[mt][nt][3], 0.f);
            if (i0 == j0)     o00 = INF;
            if (i0 == j0 + 1) o01 = INF;
            if (i1 == j0)     o10 = INF;
            if (i1 == j0 + 1) o11 = INF;
            if (!upH) {
                *(__half2*)&g_sqd[(size_t)i0 * NPTS + j0] = __floats2half2_rn(o00, o01);
                *(__half2*)&g_sqd[(size_t)i1 * NPTS + j0] = __floats2half2_rn(o10, o11);
            }
            if (lowH) {        // stage transpose for mirror (no diag in LOWER halves)
                int il = wm + mt * 16 + (lane >> 2);
                S[(jl)     * MIRS + il]     = __float2half_rn(o00);
                S[(jl + 1) * MIRS + il]     = __float2half_rn(o01);
                S[(jl)     * MIRS + il + 8] = __float2half_rn(o10);
                S[(jl + 1) * MIRS + il + 8] = __float2half_rn(o11);
            }
        }
    }

    if (low0 || low1) {
        __syncthreads();
        // stream mirror rows: row jl -> g_sqd[(col0+jl)*NPTS + row0 .. +128)
        int jl = tid;
        bool rowLow = (jl >> 7) ? low1 : low0;
        if (rowLow) {
            uint4* dst = (uint4*)&g_sqd[(size_t)(col0 + jl) * NPTS + row0];
            const uint4* srcp = (const uint4*)&S[jl * MIRS];
            #pragma unroll
            for (int q2 = 0; q2 < 16; q2++)
                dst[q2] = srcp[q2];
        }
    }
}

// ================= kernel 3: top-24 approx (fp16 scan) + exact rescoring ========
__global__ __launch_bounds__(256)
void topk_curv_kernel(const float* __restrict__ E, const float* __restrict__ ref_curv) {
    const int row  = blockIdx.x * 8 + (threadIdx.x >> 5);
    const int lane = threadIdx.x & 31;
    const float INF = __int_as_float(0x7f800000);
    const uint4* r8 = (const uint4*)(g_sqd + (size_t)row * NPTS);

    // lanes 0..KEEP-1 hold the current KEEP smallest approx values, sorted.
    float lv = INF; int li = 0;
    float T  = INF;

    #pragma unroll 1
    for (int it = 0; it < NPTS / 256; it++) {
        uint4 v = r8[it * 32 + lane];
        const __half2* hp = (const __half2*)&v;
        float2 f0 = __half22float2(hp[0]);
        float2 f1 = __half22float2(hp[1]);
        float2 f2 = __half22float2(hp[2]);
        float2 f3 = __half22float2(hp[3]);
        float m = fminf(fminf(fminf(f0.x, f0.y), fminf(f1.x, f1.y)),
                        fminf(fminf(f2.x, f2.y), fminf(f3.x, f3.y)));
        unsigned ball = __ballot_sync(FULLM, m < T);
        while (ball) {
            int src = __ffs(ball) - 1;
            ball &= ball - 1;
            uint32_t w0 = __shfl_sync(FULLM, v.x, src);
            uint32_t w1 = __shfl_sync(FULLM, v.y, src);
            uint32_t w2 = __shfl_sync(FULLM, v.z, src);
            uint32_t w3 = __shfl_sync(FULLM, v.w, src);
            int jb = (it * 32 + src) * 8;
            uint32_t ww[4] = {w0, w1, w2, w3};
            #pragma unroll
            for (int h = 0; h < 4; h++) {
                float2 fp = __half22float2(*(const __half2*)&ww[h]);
                float pv2[2] = {fp.x, fp.y};
                #pragma unroll
                for (int c = 0; c < 2; c++) {
                    float val = pv2[c];
                    if (val < T) {                 // warp-uniform
                        unsigned less = __ballot_sync(FULLM, lv < val);
                        int pos = __popc(less);
                        float pv = __shfl_up_sync(FULLM, lv, 1);
                        int   pi = __shfl_up_sync(FULLM, li, 1);
                        if (lane == pos)                      { lv = val; li = jb + h * 2 + c; }
                        else if (lane > pos && lane < KEEP)   { lv = pv;  li = pi;             }
                        T = __shfl_sync(FULLM, lv, KEEP - 1);
                    }
                }
            }
        }
    }

    // ---- exact fp32 rescoring of the KEEP candidates ----
    float4 x[4];
    const float4* Xr = (const float4*)&E[(size_t)row * DIM];
    #pragma unroll
    for (int q = 0; q < 4; q++) x[q] = Xr[q * 32 + lane];
    const float ni = g_norms[row];

    float exd = INF;
    #pragma unroll 1
    for (int c = 0; c < KEEP; c++) {
        int idx = __shfl_sync(FULLM, li, c);
        const float4* Y = (const float4*)&E[(size_t)idx * DIM];
        float s = 0.f;
        #pragma unroll
        for (int q = 0; q < 4; q++) {
            float4 y = Y[q * 32 + lane];
            s = fmaf(x[q].x, y.x, fmaf(x[q].y, y.y, fmaf(x[q].z, y.z, fmaf(x[q].w, y.w, s))));
        }
        #pragma unroll
        for (int o = 16; o; o >>= 1) s += __shfl_xor_sync(FULLM, s, o);
        if (lane == c) exd = fmaxf(ni + g_norms[idx] - 2.f * s, 0.f);
    }

    // ---- extract 15 smallest exact values (sorted), with indices ----
    float cur = exd;     // INF for lanes >= KEEP
    float myd = 0.f; int myi = 0;
    #pragma unroll 1
    for (int s = 0; s < KNN; s++) {
        float m = cur; int src = lane;
        #pragma unroll
        for (int o = 16; o; o >>= 1) {
            float om = __shfl_xor_sync(FULLM, m, o);
            int   os = __shfl_xor_sync(FULLM, src, o);
            if (om < m || (om == m && os < src)) { m = om; src = os; }
        }
        int wi = __shfl_sync(FULLM, li, src);
        if (lane == s) { myd = m; myi = wi; }
        if (lane == src) cur = INF;
    }

    // ---- curvature loss (exact, sorted ascending on lanes 0..14) ----
    float dd = (lane < KNN) ? sqrtf(fmaxf(myd, 1e-12f)) : 0.f;
    float ssum = dd;
    #pragma unroll
    for (int o = 16; o; o >>= 1) ssum += __shfl_xor_sync(FULLM, ssum, o);
    float mean = ssum / (float)KNN + 1e-8f;    // EPS_MEAN
    float df = 0.f;
    if (lane < KNN) {
        df = dd / mean - ref_curv[row * KNN + lane];
        g_knni[row * KNN + lane] = myi;
    }
    float l = df * df;
    #pragma unroll
    for (int o = 16; o; o >>= 1) l += __shfl_xor_sync(FULLM, l, o);
    if (lane == 0) atomicAdd(&g_acc[0], (double)l);
}

// ================= kernel 4: angular signature loss =================
__global__ __launch_bounds__(256)
void angular_kernel(const float* __restrict__ E, const float* __restrict__ ref_ang) {
    const int row  = blockIdx.x;
    const int tid  = threadIdx.x;
    const int lane = tid & 31;
    const int w    = tid >> 5;

    __shared__ float ei[DIM];
    __shared__ float vh[KNN][DIM];
    __shared__ float nrm[KNN];
    __shared__ float cosv[128];
    __shared__ float lsum[8];

    if (tid < 128) {
        float4 q = *(const float4*)&E[(size_t)row * DIM + tid * 4];
        *(float4*)&ei[tid * 4] = q;
    }
    if (tid >= 105 && tid < 128) cosv[tid] = __int_as_float(0x7f800000);
    __syncthreads();

    for (int j = w; j < KNN; j += 8) {
        int nb = g_knni[row * KNN + j];
        const float4* src = (const float4*)&E[(size_t)nb * DIM];
        float s = 0.f;
        for (int c4 = lane; c4 < DIM / 4; c4 += 32) {
            float4 q = src[c4];
            float4 e = *(const float4*)&ei[c4 * 4];
            float4 v; v.x = q.x - e.x; v.y = q.y - e.y; v.z = q.z - e.z; v.w = q.w - e.w;
            *(float4*)&vh[j][c4 * 4] = v;
            s = fmaf(v.x, v.x, fmaf(v.y, v.y, fmaf(v.z, v.z, fmaf(v.w, v.w, s))));
        }
        #pragma unroll
        for (int o = 16; o; o >>= 1) s += __shfl_xor_sync(FULLM, s, o);
        if (!lane) nrm[j] = fmaxf(sqrtf(s), 1e-8f);   // EPS_NORM
    }
    __syncthreads();

    for (int p = w; p < NPAIR; p += 8) {
        int jj = 0, rem = p;
        while (rem >= (KNN - 1) - jj) { rem -= (KNN - 1) - jj; jj++; }
        int kk = jj + 1 + rem;
        float s = 0.f;
        for (int c = lane; c < DIM; c += 32)
            s = fmaf(vh[jj][c], vh[kk][c], s);
        #pragma unroll
        for (int o = 16; o; o >>= 1) s += __shfl_xor_sync(FULLM, s, o);
        if (!lane) cosv[p] = s / (nrm[jj] * nrm[kk]);
    }
    __syncthreads();

    for (int k = 2; k <= 128; k <<= 1) {
        for (int j2 = k >> 1; j2 > 0; j2 >>= 1) {
            if (tid < 128) {
                int ixj = tid ^ j2;
                if (ixj > tid) {
                    float a = cosv[tid], b = cosv[ixj];
                    bool up = ((tid & k) == 0);
                    if ((a > b) == up) { cosv[tid] = b; cosv[ixj] = a; }
                }
            }
            __syncthreads();
        }
    }

    float s = 0.f;
    for (int t2 = tid; t2 < NPAIR; t2 += 256) {
        float df = cosv[t2] - ref_ang[(size_t)row * NPAIR + t2];
        s = fmaf(df, df, s);
    }
    #pragma unroll
    for (int o = 16; o; o >>= 1) s += __shfl_xor_sync(FULLM, s, o);
    if (!lane) lsum[w] = s;
    __syncthreads();
    if (tid == 0) {
        float t2 = 0.f;
        #pragma unroll
        for (int q = 0; q < 8; q++) t2 += lsum[q];
        atomicAdd(&g_acc[1], (double)t2);
    }
}

// ================= kernel 5: finalize =================
__global__ void finalize_kernel(float* out) {
    double curv = g_acc[0] / ((double)NPTS * KNN);
    double ang  = g_acc[1] / ((double)NPTS * NPAIR);
    out[0] = (float)(0.3 * curv + 0.7 * ang);
}

// ================= launch =================
extern "C" void kernel_launch(void* const* d_in, const int* in_sizes, int n_in,
                              void* d_out, int out_size) {
    const float* emb      = (const float*)d_in[0];
    const float* ref_curv = (const float*)d_in[1];
    const float* ref_ang  = (const float*)d_in[2];
    float* out = (float*)d_out;

    cudaFuncSetAttribute(gemm_bf16_kernel,
                         cudaFuncAttributeMaxDynamicSharedMemorySize, SMEM_GEMM);

    const int NTILES = 1056;   // sum over r of (floor(r/2)+1), r in 0..63

    zero_acc_kernel<<<1, 1>>>();
    prep_kernel<<<NPTS / 8, 256>>>(emb);
    gemm_bf16_kernel<<<NTILES, 256, SMEM_GEMM>>>();
    topk_curv_kernel<<<NPTS / 8, 256>>>(emb, ref_curv);
    angular_kernel<<<NPTS, 256>>>(emb, ref_ang);
    finalize_kernel<<<1, 1>>>(out);
}